// round 14
// baseline (speedup 1.0000x reference)
#include <cuda_runtime.h>
#include <cuda_bf16.h>
#include <stdint.h>
#include <math.h>

// Problem constants
#define B_TOTAL 8192
#define T_STEPS 60
#define F_IN    158
#define HDIM    32
#define G4      128
#define NBLK    128                        // 64-row blocks

typedef unsigned long long u64;
typedef ulonglong2 u64x2;

// ---------------- helpers ----------------
__device__ __forceinline__ void ffma2(u64 &acc, u64 a, u64 b) {
    asm("fma.rn.f32x2 %0, %1, %2, %0;" : "+l"(acc) : "l"(a), "l"(b));
}
__device__ __forceinline__ u64 pack2s(float x) {
    u64 r; asm("mov.b64 %0, {%1, %1};" : "=l"(r) : "f"(x)); return r;
}
__device__ __forceinline__ float2 unpack2(u64 v) {
    float2 r; asm("mov.b64 {%0, %1}, %2;" : "=f"(r.x), "=f"(r.y) : "l"(v)); return r;
}
__device__ __forceinline__ float tanha(float x) {
    float y; asm("tanh.approx.f32 %0, %1;" : "=f"(y) : "f"(x)); return y;
}
__device__ __forceinline__ float sigf(float x) {      // 0.5*tanh(x/2)+0.5
    return fmaf(0.5f, tanha(0.5f * x), 0.5f);
}
// bf16 hi/lo split of a float2 -> two packed bf16x2 words
__device__ __forceinline__ void split_pair(float2 v, uint32_t &hw, uint32_t &lw) {
    __nv_bfloat16 h0 = __float2bfloat16(v.x);
    __nv_bfloat16 h1 = __float2bfloat16(v.y);
    __nv_bfloat16 l0 = __float2bfloat16(v.x - __bfloat162float(h0));
    __nv_bfloat16 l1 = __float2bfloat16(v.y - __bfloat162float(h1));
    hw = ((uint32_t)__bfloat16_as_ushort(h1) << 16) | __bfloat16_as_ushort(h0);
    lw = ((uint32_t)__bfloat16_as_ushort(l1) << 16) | __bfloat16_as_ushort(l0);
}
// D(m16n8) += A(m16k16 row) * B(k16n8 col), bf16 in, f32 accum
__device__ __forceinline__ void mma_bf16(float d[4],
                                         uint32_t a0, uint32_t a1, uint32_t a2, uint32_t a3,
                                         uint32_t b0, uint32_t b1) {
    asm volatile(
        "mma.sync.aligned.m16n8k16.row.col.f32.bf16.bf16.f32 "
        "{%0,%1,%2,%3}, {%4,%5,%6,%7}, {%8,%9}, {%0,%1,%2,%3};"
        : "+f"(d[0]), "+f"(d[1]), "+f"(d[2]), "+f"(d[3])
        : "r"(a0), "r"(a1), "r"(a2), "r"(a3), "r"(b0), "r"(b1));
}

// =======================================================================
// Fused kernel: 128 CTAs x 256 thr, 64 batch rows each.
// Per step: mma (bf16 3-term) computes this CTA's xg tile from x -> smem
// stage; recurrence (R6 FFMA2 path) consumes it. x(t+1) reg-prefetched.
// =======================================================================
#define NTHREADS 256
#define RSTB     336                        // plane row stride bytes (conflict-free)
#define HPAD     68
#define SSTR     132                        // stage row stride (floats)

// smem byte offsets
#define OFF_W0   0                          // recurrent weights f32 [k][128]
#define OFF_W1   16384
#define OFF_W2   32768
#define OFF_WH   49152                      // Wih0 bf16-hi plane [128][336B]
#define OFF_WL   (OFF_WH + 128*RSTB)        // 92160
#define OFF_XH   (OFF_WL + 128*RSTB)        // 135168, x plane [64][336B]
#define OFF_XL   (OFF_XH + 64*RSTB)         // 156672
#define OFF_H    (OFF_XL + 64*RSTB)         // 178176, h1 then h2 (32*68*4 each)
#define OFF_STG  (OFF_H + 2*HDIM*HPAD*4)    // 195584, stage [64][132] f32
#define SMEM_BYTES (OFF_STG + 64*SSTR*4)    // 229376 B = 224 KB

// load 20 x float2-pairs for step t into regs (row = tid>>2, p = (tid&3)+4k)
__device__ __forceinline__ void load_x_regs(const float* __restrict__ xsrc,
                                            int t, int tid, float2 xr[20]) {
    const int r = tid >> 2, pb = tid & 3;
    const float* src = xsrc + (size_t)r * (T_STEPS * F_IN) + t * F_IN;
#pragma unroll
    for (int k = 0; k < 20; ++k) {
        int p = pb + 4 * k;
        xr[k] = (p < 79) ? *(const float2*)(src + 2 * p) : make_float2(0.f, 0.f);
    }
}
__device__ __forceinline__ void convert_x(char* Xh, char* Xl, int tid,
                                          const float2 xr[20]) {
    const int r = tid >> 2, pb = tid & 3;
#pragma unroll
    for (int k = 0; k < 20; ++k) {
        int p = pb + 4 * k;
        uint32_t hw, lw;
        split_pair(xr[k], hw, lw);
        int a = r * RSTB + 4 * p;
        *(uint32_t*)(Xh + a) = hw;
        *(uint32_t*)(Xl + a) = lw;
    }
}

__global__ void __launch_bounds__(NTHREADS)
lstm_fused_kernel(const float* __restrict__ x,
                  const float* __restrict__ Wih0, const float* __restrict__ Whh0,
                  const float* __restrict__ Wih1, const float* __restrict__ Whh1,
                  const float* __restrict__ W1,   const float* __restrict__ b1,
                  const float* __restrict__ W2,   float* __restrict__ out) {
    extern __shared__ char sm[];
    float* sW0 = (float*)(sm + OFF_W0);
    float* sW1 = (float*)(sm + OFF_W1);
    float* sW2 = (float*)(sm + OFF_W2);
    char*  Wh  = sm + OFF_WH;
    char*  Wl  = sm + OFF_WL;
    char*  Xh  = sm + OFF_XH;
    char*  Xl  = sm + OFF_XL;
    float* h1  = (float*)(sm + OFF_H);
    float* h2  = h1 + HDIM * HPAD;
    float* stg = (float*)(sm + OFF_STG);

    const int tid = threadIdx.x;
    const int lane = tid & 31, w = tid >> 5;
    const int blk = blockIdx.x;
    // mma decomposition: 8 warps = 4 m16-tiles x 2 n64-halves
    const int mw = w & 3, nw = w >> 2;
    const int g = lane >> 2, tq = lane & 3;
    // recurrence decomposition: warp w owns rows m0..m0+7, lane = hidden unit j
    const int j = lane, m0 = w * 8;

    // ---- recurrent weights f32 [k][128] (R6 format) ----
    for (int i = tid; i < HDIM * G4; i += NTHREADS) {
        int k = i >> 7, n = i & 127;
        sW0[i] = Whh0[n * HDIM + k];
        sW1[i] = Wih1[n * HDIM + k];
        sW2[i] = Whh1[n * HDIM + k];
    }
    // ---- Wih0 -> bf16 hi/lo planes ----
    for (int i = tid; i < 128 * 80; i += NTHREADS) {
        int n = i / 80, p = i - n * 80;
        uint32_t hw = 0, lw = 0;
        if (p < 79) {
            float2 v = *(const float2*)(Wih0 + n * F_IN + 2 * p);
            split_pair(v, hw, lw);
        }
        int a = n * RSTB + 4 * p;
        *(uint32_t*)(Wh + a) = hw;
        *(uint32_t*)(Wl + a) = lw;
    }
    for (int i = tid; i < 2 * HDIM * HPAD; i += NTHREADS) h1[i] = 0.0f;

    const float* xsrc = x + (size_t)(blk * 64) * (T_STEPS * F_IN);

    // prologue: x(0) -> regs -> planes
    float2 xr[20];
    load_x_regs(xsrc, 0, tid, xr);
    convert_x(Xh, Xl, tid, xr);
    __syncthreads();

    float c1[8], c2[8];
#pragma unroll
    for (int q = 0; q < 8; ++q) { c1[q] = 0.0f; c2[q] = 0.0f; }

    const uint32_t aoff = (16 * mw + g) * RSTB + 4 * tq;

    for (int t = 0; t < T_STEPS; ++t) {
        // prefetch x(t+1) into regs (completes under the mma below)
        if (t + 1 < T_STEPS) load_x_regs(xsrc, t + 1, tid, xr);

        // ---- mma: xg tile = x(t) @ Wih0^T (3-term bf16 split) ----
        float acc[8][4];
#pragma unroll
        for (int nt = 0; nt < 8; ++nt)
#pragma unroll
            for (int q = 0; q < 4; ++q) acc[nt][q] = 0.0f;

#pragma unroll 2
        for (int ks = 0; ks < 10; ++ks) {
            const int kb = 32 * ks;
            uint32_t ah0 = *(const uint32_t*)(Xh + aoff + kb);
            uint32_t ah1 = *(const uint32_t*)(Xh + aoff + kb + 8 * RSTB);
            uint32_t ah2 = *(const uint32_t*)(Xh + aoff + kb + 16);
            uint32_t ah3 = *(const uint32_t*)(Xh + aoff + kb + 8 * RSTB + 16);
            uint32_t al0 = *(const uint32_t*)(Xl + aoff + kb);
            uint32_t al1 = *(const uint32_t*)(Xl + aoff + kb + 8 * RSTB);
            uint32_t al2 = *(const uint32_t*)(Xl + aoff + kb + 16);
            uint32_t al3 = *(const uint32_t*)(Xl + aoff + kb + 8 * RSTB + 16);
#pragma unroll
            for (int nt = 0; nt < 8; ++nt) {
                const uint32_t boff = (uint32_t)(64 * nw + 8 * nt + g) * RSTB + 4 * tq + kb;
                uint32_t bh0 = *(const uint32_t*)(Wh + boff);
                uint32_t bh1 = *(const uint32_t*)(Wh + boff + 16);
                uint32_t bl0 = *(const uint32_t*)(Wl + boff);
                uint32_t bl1 = *(const uint32_t*)(Wl + boff + 16);
                mma_bf16(acc[nt], ah0, ah1, ah2, ah3, bh0, bh1);
                mma_bf16(acc[nt], ah0, ah1, ah2, ah3, bl0, bl1);
                mma_bf16(acc[nt], al0, al1, al2, al3, bh0, bh1);
            }
        }
        // stage D frags: stg[m][col], stride 132
        {
            const int m = 16 * mw + g;
#pragma unroll
            for (int nt = 0; nt < 8; ++nt) {
                const int col = 64 * nw + 8 * nt + 2 * tq;
                *(float2*)(stg + (size_t)m * SSTR + col)
                    = make_float2(acc[nt][0], acc[nt][1]);
                *(float2*)(stg + (size_t)(m + 8) * SSTR + col)
                    = make_float2(acc[nt][2], acc[nt][3]);
            }
        }
        __syncthreads();            // stage complete; X planes fully read

        // convert x(t+1) into the (single) plane buffer
        if (t + 1 < T_STEPS) convert_x(Xh, Xl, tid, xr);

        // ---- recurrence (R6 path), gates from stage ----
        float xg[4][8];
#pragma unroll
        for (int gg = 0; gg < 4; ++gg)
#pragma unroll
            for (int q = 0; q < 8; ++q)
                xg[gg][q] = stg[(m0 + q) * SSTR + j + 32 * gg];

        u64 racc[4][4];
#pragma unroll
        for (int gg = 0; gg < 4; ++gg)
#pragma unroll
            for (int p = 0; p < 4; ++p) racc[gg][p] = 0ULL;

#pragma unroll 4
        for (int k = 0; k < HDIM; ++k) {
            u64x2 ha = *(const u64x2*)(h1 + k * HPAD + m0);
            u64x2 hb = *(const u64x2*)(h1 + k * HPAD + m0 + 4);
            const float* wk = sW0 + k * G4 + j;
#pragma unroll
            for (int gg = 0; gg < 4; ++gg) {
                u64 wv = pack2s(wk[32 * gg]);
                ffma2(racc[gg][0], ha.x, wv);
                ffma2(racc[gg][1], ha.y, wv);
                ffma2(racc[gg][2], hb.x, wv);
                ffma2(racc[gg][3], hb.y, wv);
            }
        }

        float hn[8];
#pragma unroll
        for (int p = 0; p < 4; ++p) {
            float2 iv = unpack2(racc[0][p]);
            float2 fv = unpack2(racc[1][p]);
            float2 gv = unpack2(racc[2][p]);
            float2 ov = unpack2(racc[3][p]);
            iv.x += xg[0][2 * p]; iv.y += xg[0][2 * p + 1];
            fv.x += xg[1][2 * p]; fv.y += xg[1][2 * p + 1];
            gv.x += xg[2][2 * p]; gv.y += xg[2][2 * p + 1];
            ov.x += xg[3][2 * p]; ov.y += xg[3][2 * p + 1];
            float ca = sigf(fv.x) * c1[2 * p]     + sigf(iv.x) * tanha(gv.x);
            float cb = sigf(fv.y) * c1[2 * p + 1] + sigf(iv.y) * tanha(gv.y);
            c1[2 * p] = ca; c1[2 * p + 1] = cb;
            hn[2 * p]     = sigf(ov.x) * tanha(ca);
            hn[2 * p + 1] = sigf(ov.y) * tanha(cb);
        }
        __syncwarp();
        *(float4*)(h1 + j * HPAD + m0)     = make_float4(hn[0], hn[1], hn[2], hn[3]);
        *(float4*)(h1 + j * HPAD + m0 + 4) = make_float4(hn[4], hn[5], hn[6], hn[7]);
        __syncwarp();

#pragma unroll
        for (int gg = 0; gg < 4; ++gg)
#pragma unroll
            for (int p = 0; p < 4; ++p) racc[gg][p] = 0ULL;

#pragma unroll 4
        for (int k = 0; k < HDIM; ++k) {
            u64x2 ha = *(const u64x2*)(h1 + k * HPAD + m0);
            u64x2 hb = *(const u64x2*)(h1 + k * HPAD + m0 + 4);
            u64x2 ga = *(const u64x2*)(h2 + k * HPAD + m0);
            u64x2 gb = *(const u64x2*)(h2 + k * HPAD + m0 + 4);
            const float* wka = sW1 + k * G4 + j;
            const float* wkb = sW2 + k * G4 + j;
#pragma unroll
            for (int gg = 0; gg < 4; ++gg) {
                u64 wa = pack2s(wka[32 * gg]);
                u64 wb = pack2s(wkb[32 * gg]);
                ffma2(racc[gg][0], ha.x, wa);
                ffma2(racc[gg][1], ha.y, wa);
                ffma2(racc[gg][2], hb.x, wa);
                ffma2(racc[gg][3], hb.y, wa);
                ffma2(racc[gg][0], ga.x, wb);
                ffma2(racc[gg][1], ga.y, wb);
                ffma2(racc[gg][2], gb.x, wb);
                ffma2(racc[gg][3], gb.y, wb);
            }
        }

#pragma unroll
        for (int p = 0; p < 4; ++p) {
            float2 iv = unpack2(racc[0][p]);
            float2 fv = unpack2(racc[1][p]);
            float2 gv = unpack2(racc[2][p]);
            float2 ov = unpack2(racc[3][p]);
            float ca = sigf(fv.x) * c2[2 * p]     + sigf(iv.x) * tanha(gv.x);
            float cb = sigf(fv.y) * c2[2 * p + 1] + sigf(iv.y) * tanha(gv.y);
            c2[2 * p] = ca; c2[2 * p + 1] = cb;
            hn[2 * p]     = sigf(ov.x) * tanha(ca);
            hn[2 * p + 1] = sigf(ov.y) * tanha(cb);
        }
        __syncwarp();
        *(float4*)(h2 + j * HPAD + m0)     = make_float4(hn[0], hn[1], hn[2], hn[3]);
        *(float4*)(h2 + j * HPAD + m0 + 4) = make_float4(hn[4], hn[5], hn[6], hn[7]);
        __syncwarp();

        __syncthreads();            // stage reads + X-plane writes complete
    }

    // ---- epilogue: y = relu(c_n @ W1^T + b1) @ W2^T ----
    float* cs = stg;                // overlay [128 rows][33]
#pragma unroll
    for (int q = 0; q < 8; ++q) {
        cs[(m0 + q) * 33 + j]      = c1[q];
        cs[(64 + m0 + q) * 33 + j] = c2[q];
    }
    __syncthreads();

    if (tid < 128) {
        int L = tid >> 6, m = tid & 63;
        const float* crow = &cs[(L * 64 + m) * 33];
        float y = 0.0f;
#pragma unroll
        for (int u = 0; u < 16; ++u) {
            float s = __ldg(&b1[u]);
#pragma unroll
            for (int q = 0; q < 32; ++q) s += crow[q] * __ldg(&W1[u * 32 + q]);
            y += fmaxf(s, 0.0f) * __ldg(&W2[u]);
        }
        out[L * B_TOTAL + blk * 64 + m] = y;
    }
}

extern "C" void kernel_launch(void* const* d_in, const int* in_sizes, int n_in,
                              void* d_out, int out_size) {
    const float* x    = (const float*)d_in[0];
    const float* Wih0 = (const float*)d_in[1];
    const float* Whh0 = (const float*)d_in[2];
    const float* Wih1 = (const float*)d_in[3];
    const float* Whh1 = (const float*)d_in[4];
    const float* W1   = (const float*)d_in[5];
    const float* b1   = (const float*)d_in[6];
    const float* W2   = (const float*)d_in[7];
    float* out        = (float*)d_out;

    cudaFuncSetAttribute(lstm_fused_kernel,
                         cudaFuncAttributeMaxDynamicSharedMemorySize, SMEM_BYTES);
    lstm_fused_kernel<<<NBLK, NTHREADS, SMEM_BYTES>>>(x, Wih0, Whh0, Wih1, Whh1,
                                                      W1, b1, W2, out);
}

// round 15
// speedup vs baseline: 1.1521x; 1.1521x over previous
#include <cuda_runtime.h>
#include <cuda_bf16.h>
#include <stdint.h>
#include <math.h>

// Problem constants
#define B_TOTAL 8192
#define T_STEPS 60
#define F_IN    158
#define HDIM    32
#define G4      128
#define NBLK    128                        // 64-row blocks

typedef unsigned long long u64;
typedef ulonglong2 u64x2;

// ---------------- helpers ----------------
__device__ __forceinline__ void ffma2(u64 &acc, u64 a, u64 b) {
    asm("fma.rn.f32x2 %0, %1, %2, %0;" : "+l"(acc) : "l"(a), "l"(b));
}
__device__ __forceinline__ u64 pack2(float x, float y) {
    u64 r; asm("mov.b64 %0, {%1, %2};" : "=l"(r) : "f"(x), "f"(y)); return r;
}
__device__ __forceinline__ u64 pack2s(float x) {
    u64 r; asm("mov.b64 %0, {%1, %1};" : "=l"(r) : "f"(x)); return r;
}
__device__ __forceinline__ float2 unpack2(u64 v) {
    float2 r; asm("mov.b64 {%0, %1}, %2;" : "=f"(r.x), "=f"(r.y) : "l"(v)); return r;
}
__device__ __forceinline__ float tanha(float x) {
    float y; asm("tanh.approx.f32 %0, %1;" : "=f"(y) : "f"(x)); return y;
}
__device__ __forceinline__ float sigf(float x) {      // 0.5*tanh(x/2)+0.5
    return fmaf(0.5f, tanha(0.5f * x), 0.5f);
}
__device__ __forceinline__ void split_pair(float2 v, uint32_t &hw, uint32_t &lw) {
    __nv_bfloat16 h0 = __float2bfloat16(v.x);
    __nv_bfloat16 h1 = __float2bfloat16(v.y);
    __nv_bfloat16 l0 = __float2bfloat16(v.x - __bfloat162float(h0));
    __nv_bfloat16 l1 = __float2bfloat16(v.y - __bfloat162float(h1));
    hw = ((uint32_t)__bfloat16_as_ushort(h1) << 16) | __bfloat16_as_ushort(h0);
    lw = ((uint32_t)__bfloat16_as_ushort(l1) << 16) | __bfloat16_as_ushort(l0);
}
__device__ __forceinline__ void mma_bf16(float d[4],
                                         uint32_t a0, uint32_t a1, uint32_t a2, uint32_t a3,
                                         uint32_t b0, uint32_t b1) {
    asm volatile(
        "mma.sync.aligned.m16n8k16.row.col.f32.bf16.bf16.f32 "
        "{%0,%1,%2,%3}, {%4,%5,%6,%7}, {%8,%9}, {%0,%1,%2,%3};"
        : "+f"(d[0]), "+f"(d[1]), "+f"(d[2]), "+f"(d[3])
        : "r"(a0), "r"(a1), "r"(a2), "r"(a3), "r"(b0), "r"(b1));
}
#define BAR_SYNC(id, cnt)   asm volatile("bar.sync %0, %1;"   :: "r"(id), "r"(cnt) : "memory")
#define BAR_ARRIVE(id, cnt) asm volatile("bar.arrive %0, %1;" :: "r"(id), "r"(cnt) : "memory")

// =======================================================================
// Warp-specialized fused kernel: 128 CTAs x 512 thr, 64 batch rows each.
// Warps 0-7 (producers): bf16-mma xg(t) -> stage. Warps 8-15 (consumers):
// R6 FFMA2 recurrence reading gates from stage. Named-barrier handshake.
// =======================================================================
#define NTHREADS 512
#define RSTB     336                        // plane row stride bytes
#define HPAD     68
#define SSTR     132                        // stage row stride (floats)

#define OFF_W0   0
#define OFF_W1   16384
#define OFF_W2   32768
#define OFF_WH   49152
#define OFF_WL   (OFF_WH + 128*RSTB)
#define OFF_XH   (OFF_WL + 128*RSTB)
#define OFF_XL   (OFF_XH + 64*RSTB)
#define OFF_H    (OFF_XL + 64*RSTB)
#define OFF_STG  (OFF_H + 2*HDIM*HPAD*4)
#define SMEM_BYTES (OFF_STG + 64*SSTR*4)    // 229376 B

// producers: 256 threads load 20 float2 each (row = ptid>>2, p = (ptid&3)+4k)
__device__ __forceinline__ void load_x_regs(const float* __restrict__ xsrc,
                                            int t, int ptid, float2 xr[20]) {
    const int r = ptid >> 2, pb = ptid & 3;
    const float* src = xsrc + (size_t)r * (T_STEPS * F_IN) + t * F_IN;
#pragma unroll
    for (int k = 0; k < 20; ++k) {
        int p = pb + 4 * k;
        xr[k] = (p < 79) ? *(const float2*)(src + 2 * p) : make_float2(0.f, 0.f);
    }
}
__device__ __forceinline__ void convert_x(char* Xh, char* Xl, int ptid,
                                          const float2 xr[20]) {
    const int r = ptid >> 2, pb = ptid & 3;
#pragma unroll
    for (int k = 0; k < 20; ++k) {
        int p = pb + 4 * k;
        uint32_t hw, lw;
        split_pair(xr[k], hw, lw);
        int a = r * RSTB + 4 * p;
        *(uint32_t*)(Xh + a) = hw;
        *(uint32_t*)(Xl + a) = lw;
    }
}

__global__ void __launch_bounds__(NTHREADS, 1)
lstm_ws_kernel(const float* __restrict__ x,
               const float* __restrict__ Wih0, const float* __restrict__ Whh0,
               const float* __restrict__ Wih1, const float* __restrict__ Whh1,
               const float* __restrict__ W1,   const float* __restrict__ b1,
               const float* __restrict__ W2,   float* __restrict__ out) {
    extern __shared__ char sm[];
    float* sW0 = (float*)(sm + OFF_W0);
    float* sW1 = (float*)(sm + OFF_W1);
    float* sW2 = (float*)(sm + OFF_W2);
    char*  Wh  = sm + OFF_WH;
    char*  Wl  = sm + OFF_WL;
    char*  Xh  = sm + OFF_XH;
    char*  Xl  = sm + OFF_XL;
    float* h1  = (float*)(sm + OFF_H);
    float* h2  = h1 + HDIM * HPAD;
    float* stg = (float*)(sm + OFF_STG);

    const int tid = threadIdx.x;
    const int lane = tid & 31, w = tid >> 5;
    const int blk = blockIdx.x;
    const float* xsrc = x + (size_t)(blk * 64) * (T_STEPS * F_IN);

    // ---- cooperative init (all 512 threads) ----
    for (int i = tid; i < HDIM * G4; i += NTHREADS) {
        int k = i >> 7, n = i & 127;
        sW0[i] = Whh0[n * HDIM + k];
        sW1[i] = Wih1[n * HDIM + k];
        sW2[i] = Whh1[n * HDIM + k];
    }
    for (int i = tid; i < 128 * 80; i += NTHREADS) {
        int n = i / 80, p = i - n * 80;
        uint32_t hw = 0, lw = 0;
        if (p < 79) {
            float2 v = *(const float2*)(Wih0 + n * F_IN + 2 * p);
            split_pair(v, hw, lw);
        }
        int a = n * RSTB + 4 * p;
        *(uint32_t*)(Wh + a) = hw;
        *(uint32_t*)(Wl + a) = lw;
    }
    for (int i = tid; i < 2 * HDIM * HPAD; i += NTHREADS) h1[i] = 0.0f;
    __syncthreads();

    float c1[8], c2[8];
#pragma unroll
    for (int q = 0; q < 8; ++q) { c1[q] = 0.0f; c2[q] = 0.0f; }

    if (w < 8) {
        // =============== PRODUCER: warps 0-7 ===============
        const int ptid = tid;                       // 0..255
        const int mw = w & 3, nw = w >> 2;          // 4 m16 x 2 n64
        const int g = lane >> 2, tq = lane & 3;
        const uint32_t aoff = (16 * mw + g) * RSTB + 4 * tq;

        float2 xr[20];
        load_x_regs(xsrc, 0, ptid, xr);
        convert_x(Xh, Xl, ptid, xr);
        BAR_SYNC(3, 256);                           // x(0) planes ready

        for (int t = 0; t < T_STEPS; ++t) {
            if (t + 1 < T_STEPS) load_x_regs(xsrc, t + 1, ptid, xr);

            float acc[8][4];
#pragma unroll
            for (int nt = 0; nt < 8; ++nt)
#pragma unroll
                for (int q = 0; q < 4; ++q) acc[nt][q] = 0.0f;

#pragma unroll 2
            for (int ks = 0; ks < 10; ++ks) {
                const int kb = 32 * ks;
                uint32_t ah0 = *(const uint32_t*)(Xh + aoff + kb);
                uint32_t ah1 = *(const uint32_t*)(Xh + aoff + kb + 8 * RSTB);
                uint32_t ah2 = *(const uint32_t*)(Xh + aoff + kb + 16);
                uint32_t ah3 = *(const uint32_t*)(Xh + aoff + kb + 8 * RSTB + 16);
                uint32_t al0 = *(const uint32_t*)(Xl + aoff + kb);
                uint32_t al1 = *(const uint32_t*)(Xl + aoff + kb + 8 * RSTB);
                uint32_t al2 = *(const uint32_t*)(Xl + aoff + kb + 16);
                uint32_t al3 = *(const uint32_t*)(Xl + aoff + kb + 8 * RSTB + 16);
#pragma unroll
                for (int nt = 0; nt < 8; ++nt) {
                    const uint32_t boff = (uint32_t)(64 * nw + 8 * nt + g) * RSTB + 4 * tq + kb;
                    uint32_t bh0 = *(const uint32_t*)(Wh + boff);
                    uint32_t bh1 = *(const uint32_t*)(Wh + boff + 16);
                    uint32_t bl0 = *(const uint32_t*)(Wl + boff);
                    uint32_t bl1 = *(const uint32_t*)(Wl + boff + 16);
                    mma_bf16(acc[nt], ah0, ah1, ah2, ah3, bh0, bh1);
                    mma_bf16(acc[nt], ah0, ah1, ah2, ah3, bl0, bl1);
                    mma_bf16(acc[nt], al0, al1, al2, al3, bh0, bh1);
                }
            }

            BAR_SYNC(2, 512);                       // consumers done reading stage
            {
                const int m = 16 * mw + g;
#pragma unroll
                for (int nt = 0; nt < 8; ++nt) {
                    const int col = 64 * nw + 8 * nt + 2 * tq;
                    *(float2*)(stg + (size_t)m * SSTR + col)
                        = make_float2(acc[nt][0], acc[nt][1]);
                    *(float2*)(stg + (size_t)(m + 8) * SSTR + col)
                        = make_float2(acc[nt][2], acc[nt][3]);
                }
            }
            BAR_ARRIVE(1, 512);                     // stage(t) full

            if (t + 1 < T_STEPS) convert_x(Xh, Xl, ptid, xr);
            BAR_SYNC(3, 256);                       // planes for t+1 ready
        }
    } else {
        // =============== CONSUMER: warps 8-15 ===============
        const int w2 = w - 8;
        const int j = lane, m0 = w2 * 8;

        BAR_ARRIVE(2, 512);                         // stage initially "empty"

        for (int t = 0; t < T_STEPS; ++t) {
            BAR_SYNC(1, 512);                       // stage(t) full

            u64 racc[4][4];
#pragma unroll
            for (int gg = 0; gg < 4; ++gg)
#pragma unroll
                for (int p = 0; p < 4; ++p) {
                    float a = stg[(m0 + 2 * p)     * SSTR + j + 32 * gg];
                    float b = stg[(m0 + 2 * p + 1) * SSTR + j + 32 * gg];
                    racc[gg][p] = pack2(a, b);      // seed acc with xg
                }
            BAR_ARRIVE(2, 512);                     // done reading stage

            // ---- layer 1: acc += h1 @ Whh0^T ----
#pragma unroll 4
            for (int k = 0; k < HDIM; ++k) {
                u64x2 ha = *(const u64x2*)(h1 + k * HPAD + m0);
                u64x2 hb = *(const u64x2*)(h1 + k * HPAD + m0 + 4);
                const float* wk = sW0 + k * G4 + j;
#pragma unroll
                for (int gg = 0; gg < 4; ++gg) {
                    u64 wv = pack2s(wk[32 * gg]);
                    ffma2(racc[gg][0], ha.x, wv);
                    ffma2(racc[gg][1], ha.y, wv);
                    ffma2(racc[gg][2], hb.x, wv);
                    ffma2(racc[gg][3], hb.y, wv);
                }
            }

            float hn[8];
#pragma unroll
            for (int p = 0; p < 4; ++p) {
                float2 iv = unpack2(racc[0][p]);
                float2 fv = unpack2(racc[1][p]);
                float2 gv = unpack2(racc[2][p]);
                float2 ov = unpack2(racc[3][p]);
                float ca = sigf(fv.x) * c1[2 * p]     + sigf(iv.x) * tanha(gv.x);
                float cb = sigf(fv.y) * c1[2 * p + 1] + sigf(iv.y) * tanha(gv.y);
                c1[2 * p] = ca; c1[2 * p + 1] = cb;
                hn[2 * p]     = sigf(ov.x) * tanha(ca);
                hn[2 * p + 1] = sigf(ov.y) * tanha(cb);
            }
            __syncwarp();
            *(float4*)(h1 + j * HPAD + m0)     = make_float4(hn[0], hn[1], hn[2], hn[3]);
            *(float4*)(h1 + j * HPAD + m0 + 4) = make_float4(hn[4], hn[5], hn[6], hn[7]);
            __syncwarp();

            // ---- layer 2: acc = h1_new @ Wih1^T + h2 @ Whh1^T ----
#pragma unroll
            for (int gg = 0; gg < 4; ++gg)
#pragma unroll
                for (int p = 0; p < 4; ++p) racc[gg][p] = 0ULL;

#pragma unroll 4
            for (int k = 0; k < HDIM; ++k) {
                u64x2 ha = *(const u64x2*)(h1 + k * HPAD + m0);
                u64x2 hb = *(const u64x2*)(h1 + k * HPAD + m0 + 4);
                u64x2 ga = *(const u64x2*)(h2 + k * HPAD + m0);
                u64x2 gb = *(const u64x2*)(h2 + k * HPAD + m0 + 4);
                const float* wka = sW1 + k * G4 + j;
                const float* wkb = sW2 + k * G4 + j;
#pragma unroll
                for (int gg = 0; gg < 4; ++gg) {
                    u64 wa = pack2s(wka[32 * gg]);
                    u64 wb = pack2s(wkb[32 * gg]);
                    ffma2(racc[gg][0], ha.x, wa);
                    ffma2(racc[gg][1], ha.y, wa);
                    ffma2(racc[gg][2], hb.x, wa);
                    ffma2(racc[gg][3], hb.y, wa);
                    ffma2(racc[gg][0], ga.x, wb);
                    ffma2(racc[gg][1], ga.y, wb);
                    ffma2(racc[gg][2], gb.x, wb);
                    ffma2(racc[gg][3], gb.y, wb);
                }
            }

#pragma unroll
            for (int p = 0; p < 4; ++p) {
                float2 iv = unpack2(racc[0][p]);
                float2 fv = unpack2(racc[1][p]);
                float2 gv = unpack2(racc[2][p]);
                float2 ov = unpack2(racc[3][p]);
                float ca = sigf(fv.x) * c2[2 * p]     + sigf(iv.x) * tanha(gv.x);
                float cb = sigf(fv.y) * c2[2 * p + 1] + sigf(iv.y) * tanha(gv.y);
                c2[2 * p] = ca; c2[2 * p + 1] = cb;
                hn[2 * p]     = sigf(ov.x) * tanha(ca);
                hn[2 * p + 1] = sigf(ov.y) * tanha(cb);
            }
            __syncwarp();
            *(float4*)(h2 + j * HPAD + m0)     = make_float4(hn[0], hn[1], hn[2], hn[3]);
            *(float4*)(h2 + j * HPAD + m0 + 4) = make_float4(hn[4], hn[5], hn[6], hn[7]);
            __syncwarp();
        }
    }

    __syncthreads();               // everyone past the loop; stage free

    // ---- epilogue: y = relu(c_n @ W1^T + b1) @ W2^T ----
    float* cs = stg;               // overlay [128 rows][33]
    if (w >= 8) {
        const int w2 = w - 8, j = lane, m0 = w2 * 8;
#pragma unroll
        for (int q = 0; q < 8; ++q) {
            cs[(m0 + q) * 33 + j]      = c1[q];
            cs[(64 + m0 + q) * 33 + j] = c2[q];
        }
    }
    __syncthreads();

    if (tid < 128) {
        int L = tid >> 6, m = tid & 63;
        const float* crow = &cs[(L * 64 + m) * 33];
        float y = 0.0f;
#pragma unroll
        for (int u = 0; u < 16; ++u) {
            float s = __ldg(&b1[u]);
#pragma unroll
            for (int q = 0; q < 32; ++q) s += crow[q] * __ldg(&W1[u * 32 + q]);
            y += fmaxf(s, 0.0f) * __ldg(&W2[u]);
        }
        out[L * B_TOTAL + blk * 64 + m] = y;
    }
}

extern "C" void kernel_launch(void* const* d_in, const int* in_sizes, int n_in,
                              void* d_out, int out_size) {
    const float* x    = (const float*)d_in[0];
    const float* Wih0 = (const float*)d_in[1];
    const float* Whh0 = (const float*)d_in[2];
    const float* Wih1 = (const float*)d_in[3];
    const float* Whh1 = (const float*)d_in[4];
    const float* W1   = (const float*)d_in[5];
    const float* b1   = (const float*)d_in[6];
    const float* W2   = (const float*)d_in[7];
    float* out        = (float*)d_out;

    cudaFuncSetAttribute(lstm_ws_kernel,
                         cudaFuncAttributeMaxDynamicSharedMemorySize, SMEM_BYTES);
    lstm_ws_kernel<<<NBLK, NTHREADS, SMEM_BYTES>>>(x, Wih0, Whh0, Wih1, Whh1,
                                                   W1, b1, W2, out);
}